// round 1
// baseline (speedup 1.0000x reference)
#include <cuda_runtime.h>
#include <math.h>

// ---------------- problem constants ----------------
#define NB   64
#define LT   1024
#define KK   64
#define DD   300
#define HH   5
#define ET   2048
#define EI   512
#define HD   1500   // H*D
#define NLAYERS 2

// ---------------- scratch (device globals; allocation-free) ----------------
__device__ float g_h   [(size_t)NB*LT*HD];     // GAT projections (txt)
__device__ float g_y   [(size_t)NB*LT*DD];     // txt layer-0 output
__device__ float g_x   [(size_t)NB*(LT+1)*DD]; // txt layer-1 output + c row at index LT
__device__ float g_himg[(size_t)NB*KK*HD];     // GAT projections (img)
__device__ float g_v3a [(size_t)NB*KK*DD];
__device__ float g_v3b [(size_t)NB*KK*DD];
__device__ float g_asrc[NB*LT*HH];
__device__ float g_adst[NB*LT*HH];
__device__ float g_e   [NB*ET*HH];
__device__ float g_al  [NB*ET*HH];
__device__ float g_asrci[NB*KK*HH];
__device__ float g_adsti[NB*KK*HH];
__device__ float g_ei_ [NB*EI*HH];
__device__ float g_ali [NB*EI*HH];
__device__ int   g_offt[NB*(LT+1)];
__device__ int   g_eidt[NB*ET];
__device__ int   g_offi[KK+1];
__device__ int   g_eidi[EI];
__device__ float g_patok[NB*LT];
__device__ float g_panp [NB*(LT+1)];
__device__ float g_tbar [NB*DD];
__device__ float g_tbar2[NB*DD];

__device__ __forceinline__ float wredsum(float v){
    #pragma unroll
    for (int o=16;o;o>>=1) v += __shfl_down_sync(0xffffffffu, v, o);
    return v;
}

// ---------------- CSR build (counting sort per batch) ----------------
__global__ void k_csr(const int* __restrict__ EIp, long eiStride, int nodes, int E,
                      int* __restrict__ off, int* __restrict__ eid, int perBatch)
{
    int n = blockIdx.x;
    __shared__ int cnt[LT+1];
    __shared__ int cur[LT];
    for (int i=threadIdx.x; i<=nodes; i+=blockDim.x) cnt[i]=0;
    __syncthreads();
    const int* dstp = EIp + (size_t)eiStride*n + E;
    for (int j=threadIdx.x; j<E; j+=blockDim.x) atomicAdd(&cnt[dstp[j]+1], 1);
    __syncthreads();
    if (threadIdx.x==0){
        int run=0;
        for (int i=0;i<=nodes;i++){ run += cnt[i]; cnt[i]=run; }
    }
    __syncthreads();
    int* offg = off + (perBatch ? n*(nodes+1) : 0);
    for (int i=threadIdx.x; i<=nodes; i+=blockDim.x) offg[i]=cnt[i];
    for (int i=threadIdx.x; i<nodes;  i+=blockDim.x) cur[i]=cnt[i];
    __syncthreads();
    int* eidg = eid + (perBatch ? n*E : 0);
    for (int j=threadIdx.x; j<E; j+=blockDim.x){
        int d = dstp[j];
        int pos = atomicAdd(&cur[d], 1);
        eidg[pos] = j;
    }
}

// ---------------- row dot + masked softmax (pa_token / pa_np) ----------------
__global__ void k_pa(const float* __restrict__ X, long xstride, int Lrow,
                     const float* __restrict__ w, const float* __restrict__ bsc,
                     const int* __restrict__ mask, float* __restrict__ out)
{
    int n = blockIdx.x;
    __shared__ float s[LT+1];
    __shared__ float red[32];
    int tid=threadIdx.x, warp=tid>>5, lane=tid&31;
    float bb = bsc[0];
    for (int l=warp; l<Lrow; l+=32){
        const float* row = X + (size_t)n*xstride + (size_t)l*DD;
        float acc=0.f;
        for (int d=lane; d<DD; d+=32) acc += row[d]*w[d];
        acc = wredsum(acc);
        if (lane==0) s[l] = mask[n*Lrow+l] ? -1e30f : acc+bb;
    }
    __syncthreads();
    float m=-1e30f;
    for (int l=tid; l<Lrow; l+=1024) m = fmaxf(m, s[l]);
    #pragma unroll
    for (int o=16;o;o>>=1) m = fmaxf(m, __shfl_down_sync(0xffffffffu, m, o));
    if (lane==0) red[warp]=m;
    __syncthreads();
    if (tid==0){ float v=red[0]; for(int i=1;i<32;i++) v=fmaxf(v,red[i]); red[0]=v; }
    __syncthreads();
    m = red[0];
    __syncthreads();
    float sum=0.f;
    for (int l=tid; l<Lrow; l+=1024){ float p=expf(s[l]-m); s[l]=p; sum+=p; }
    sum = wredsum(sum);
    if (lane==0) red[warp]=sum;
    __syncthreads();
    if (tid==0){ float v=0.f; for(int i=0;i<32;i++) v+=red[i]; red[0]=v; }
    __syncthreads();
    float inv = 1.f/red[0];
    for (int l=tid; l<Lrow; l+=1024) out[n*Lrow+l] = s[l]*inv;
}

// ---------------- weighted row-sum: tbar[n,d] = sum_l p[n,l] * X[n,l,d] ----------------
__global__ void k_wsum(const float* __restrict__ X, long xstride, int Lrow,
                       const float* __restrict__ p, float* __restrict__ out)
{
    int n = blockIdx.x; int d = threadIdx.x;
    if (d >= DD) return;
    const float* Xb = X + (size_t)n*xstride;
    const float* pb = p + (size_t)n*Lrow;
    float acc=0.f;
    for (int l=0; l<Lrow; l++) acc += pb[l]*Xb[(size_t)l*DD+d];
    out[n*DD+d] = acc;
}

// ---------------- a = scale * <tbar[n], V[n,k,:]> ----------------
__global__ void k_dotout(const float* __restrict__ tb, const float* __restrict__ V,
                         float* __restrict__ out, int colOff)
{
    int n = blockIdx.x;
    int warp = threadIdx.x>>5, lane = threadIdx.x&31;
    for (int k=warp; k<KK; k+=16){
        const float* v = V + ((size_t)n*KK + k)*DD;
        const float* t = tb + (size_t)n*DD;
        float acc=0.f;
        for (int d=lane; d<DD; d+=32) acc += t[d]*v[d];
        acc = wredsum(acc);
        if (lane==0) out[n*128 + colOff + k] = acc * 0.05773502691896258f; // 1/sqrt(300)
    }
}

// ---------------- c[n,d] = sum_l score*t2 -> g_x row LT ----------------
__global__ void k_c(const float* __restrict__ score, const float* __restrict__ t2,
                    float* __restrict__ xbuf)
{
    int n=blockIdx.x, d=threadIdx.x;
    if (d >= DD) return;
    const float* sb = score + (size_t)n*LT*DD;
    const float* tb = t2    + (size_t)n*LT*DD;
    float acc=0.f;
    for (int l=0; l<LT; l++) acc += sb[(size_t)l*DD+d]*tb[(size_t)l*DD+d];
    xbuf[(size_t)n*(LT+1)*DD + (size_t)LT*DD + d] = acc;
}

// ---------------- SGEMM: C[M,N] = A[M,K] * B[K,N], M % 128 == 0 ----------------
__global__ void k_gemm(const float* __restrict__ A, const float* __restrict__ B,
                       float* __restrict__ C, int M, int N, int K)
{
    __shared__ float As[16][128];
    __shared__ float Bs[16][128];
    int bm = blockIdx.y*128, bn = blockIdx.x*128;
    int tid = threadIdx.x;
    int tr = tid/16, tc = tid%16;
    float acc[8][8];
    #pragma unroll
    for (int i=0;i<8;i++)
        #pragma unroll
        for (int j=0;j<8;j++) acc[i][j]=0.f;

    for (int k0=0; k0<K; k0+=16){
        #pragma unroll
        for (int i=0;i<8;i++){
            int idx = tid + i*256; int m = idx>>4; int k = idx&15;
            int gk = k0+k;
            As[k][m] = (gk < K) ? A[(size_t)(bm+m)*K + gk] : 0.f;
        }
        #pragma unroll
        for (int i=0;i<8;i++){
            int idx = tid + i*256; int k = idx>>7; int nn = idx&127;
            int gk = k0+k, gn = bn+nn;
            Bs[k][nn] = (gk < K && gn < N) ? B[(size_t)gk*N + gn] : 0.f;
        }
        __syncthreads();
        #pragma unroll
        for (int k=0;k<16;k++){
            float af[8], bf[8];
            #pragma unroll
            for (int i=0;i<8;i++) af[i]=As[k][tr*8+i];
            #pragma unroll
            for (int j=0;j<8;j++) bf[j]=Bs[k][tc*8+j];
            #pragma unroll
            for (int i=0;i<8;i++)
                #pragma unroll
                for (int j=0;j<8;j++) acc[i][j] += af[i]*bf[j];
        }
        __syncthreads();
    }
    #pragma unroll
    for (int i=0;i<8;i++){
        size_t gm = bm + tr*8 + i;
        #pragma unroll
        for (int j=0;j<8;j++){
            int gn = bn + tc*8 + j;
            if (gn < N) C[gm*N + gn] = acc[i][j];
        }
    }
}

// ---------------- attention logits per node/head ----------------
__global__ void k_scores(const float* __restrict__ H, const float* __restrict__ aS,
                         const float* __restrict__ aD,
                         float* __restrict__ asrc, float* __restrict__ adst)
{
    int bn = blockIdx.x;                // n*nodes + node
    int h = threadIdx.x>>5, lane = threadIdx.x&31;
    const float* row = H + (size_t)bn*HD + h*DD;
    float s1=0.f, s2=0.f;
    for (int d=lane; d<DD; d+=32){ float v=row[d]; s1 += v*aS[h*DD+d]; s2 += v*aD[h*DD+d]; }
    s1 = wredsum(s1); s2 = wredsum(s2);
    if (lane==0){ asrc[bn*HH+h]=s1; adst[bn*HH+h]=s2; }
}

// ---------------- per-edge leaky_relu(a_src[src]+a_dst[dst]) ----------------
__global__ void k_edge(const int* __restrict__ EIp, long eiStride, int nodes, int E,
                       const float* __restrict__ asrc, const float* __restrict__ adst,
                       float* __restrict__ ebuf, int total)
{
    int idx = blockIdx.x*blockDim.x + threadIdx.x;
    if (idx >= total) return;
    int h = idx % HH;
    int j = (idx/HH) % E;
    int n = idx/(HH*E);
    int src = EIp[(size_t)eiStride*n + j];
    int dst = EIp[(size_t)eiStride*n + E + j];
    float e = asrc[((size_t)n*nodes+src)*HH+h] + adst[((size_t)n*nodes+dst)*HH+h];
    ebuf[idx] = e > 0.f ? e : 0.2f*e;
}

// ---------------- per-(n,dst,h) softmax over in-edges -> alpha ----------------
__global__ void k_alpha(const int* __restrict__ off, const int* __restrict__ eid, int perBatch,
                        const float* __restrict__ ebuf, float* __restrict__ alpha,
                        int nodes, int E, int total)
{
    int idx = blockIdx.x*blockDim.x + threadIdx.x;
    if (idx >= total) return;
    int h = idx % HH;
    int node = (idx/HH) % nodes;
    int n = idx/(HH*nodes);
    const int* o  = off + (perBatch ? n*(nodes+1) : 0);
    const int* ee = eid + (perBatch ? n*E : 0);
    int s=o[node], t=o[node+1];
    if (s==t) return;
    float m=-1e30f;
    for (int q=s;q<t;q++) m = fmaxf(m, ebuf[((size_t)n*E + ee[q])*HH + h]);
    float den=0.f;
    for (int q=s;q<t;q++) den += expf(ebuf[((size_t)n*E + ee[q])*HH + h]-m);
    float inv = 1.f/(den + 1e-16f);
    for (int q=s;q<t;q++){
        size_t ix = ((size_t)n*E + ee[q])*HH + h;
        alpha[ix] = expf(ebuf[ix]-m)*inv;
    }
}

// ---------------- aggregate + head-mean + bias + mask + relu + layernorm ----------------
__global__ void k_agg(const float* __restrict__ H, const float* __restrict__ alpha,
                      const int* __restrict__ off, const int* __restrict__ eid, int perBatch,
                      const int* __restrict__ EIp, long eiStride,
                      const float* __restrict__ bias, const int* __restrict__ gnnMask,
                      const float* __restrict__ lng, const float* __restrict__ lnb,
                      float* __restrict__ out, long outBatchStride, int nodes, int E)
{
    int node = blockIdx.x, n = blockIdx.y;
    int tid = threadIdx.x;               // 128 threads
    const int* o  = off + (perBatch ? n*(nodes+1) : 0);
    const int* ee = eid + (perBatch ? n*E : 0);
    int s=o[node], t=o[node+1];
    const float* Hb  = H + (size_t)n*nodes*HD;
    const float* al0 = alpha + (size_t)n*E*HH;
    const int* srcp  = EIp + (size_t)eiStride*n;
    int d0=tid, d1=tid+128, d2=tid+256;
    float a0=0.f, a1=0.f, a2=0.f;
    for (int q=s;q<t;q++){
        int j = ee[q];
        int src = srcp[j];
        const float* hr = Hb + (size_t)src*HD;
        const float* al = al0 + (size_t)j*HH;
        #pragma unroll
        for (int h=0;h<HH;h++){
            float a = al[h];
            a0 += a*hr[h*DD+d0];
            a1 += a*hr[h*DD+d1];
            if (d2<DD) a2 += a*hr[h*DD+d2];
        }
    }
    bool msk = (gnnMask != nullptr) && (gnnMask[n] != 0);
    float g0 = a0*0.2f + bias[d0];
    float g1 = a1*0.2f + bias[d1];
    float g2 = (d2<DD) ? a2*0.2f + bias[d2] : 0.f;
    if (msk){ g0=0.f; g1=0.f; g2=0.f; }
    float r0 = fmaxf(g0,0.f), r1 = fmaxf(g1,0.f), r2 = fmaxf(g2,0.f);

    __shared__ float sS[4], sQ[4];
    int warp = tid>>5, lane = tid&31;
    float lsum = r0 + r1 + ((d2<DD)? r2 : 0.f);
    float lsq  = r0*r0 + r1*r1 + ((d2<DD)? r2*r2 : 0.f);
    lsum = wredsum(lsum); lsq = wredsum(lsq);
    if (lane==0){ sS[warp]=lsum; sQ[warp]=lsq; }
    __syncthreads();
    if (tid==0){
        float S=0.f, Q=0.f;
        for (int w=0;w<4;w++){ S+=sS[w]; Q+=sQ[w]; }
        sS[0]=S; sQ[0]=Q;
    }
    __syncthreads();
    float mu  = sS[0]*(1.f/300.f);
    float var = sQ[0]*(1.f/300.f) - mu*mu;
    float rstd = rsqrtf(var + 1e-5f);
    float* orow = out + (size_t)n*outBatchStride + (size_t)node*DD;
    orow[d0] = (r0-mu)*rstd*lng[d0] + lnb[d0];
    orow[d1] = (r1-mu)*rstd*lng[d1] + lnb[d1];
    if (d2<DD) orow[d2] = (r2-mu)*rstd*lng[d2] + lnb[d2];
}

// ---------------- launch ----------------
extern "C" void kernel_launch(void* const* d_in, const int* in_sizes, int n_in,
                              void* d_out, int out_size)
{
    const float* t2    = (const float*)d_in[0];
    const float* v2    = (const float*)d_in[1];
    const float* score = (const float*)d_in[2];
    const int*   ei_t  = (const int*)  d_in[3];
    const int*   gnn   = (const int*)  d_in[4];
    const int*   kpm   = (const int*)  d_in[5];
    const int*   npm   = (const int*)  d_in[6];
    const int*   ei_i  = (const int*)  d_in[7];
    const float* txtW  = (const float*)d_in[8];
    const float* txtAS = (const float*)d_in[9];
    const float* txtAD = (const float*)d_in[10];
    const float* txtB  = (const float*)d_in[11];
    const float* imgW  = (const float*)d_in[12];
    const float* imgAS = (const float*)d_in[13];
    const float* imgAD = (const float*)d_in[14];
    const float* imgB  = (const float*)d_in[15];
    const float* w1    = (const float*)d_in[16];
    const float* b1    = (const float*)d_in[17];
    const float* w2    = (const float*)d_in[18];
    const float* b2    = (const float*)d_in[19];
    const float* lng   = (const float*)d_in[20];
    const float* lnb   = (const float*)d_in[21];
    float* out = (float*)d_out;

    float *p_h,*p_y,*p_x,*p_himg,*p_v3a,*p_v3b;
    float *p_asrc,*p_adst,*p_e,*p_al,*p_asrci,*p_adsti,*p_ei,*p_ali;
    float *p_patok,*p_panp,*p_tbar,*p_tbar2;
    int *p_offt,*p_eidt,*p_offi,*p_eidi;
    cudaGetSymbolAddress((void**)&p_h, g_h);
    cudaGetSymbolAddress((void**)&p_y, g_y);
    cudaGetSymbolAddress((void**)&p_x, g_x);
    cudaGetSymbolAddress((void**)&p_himg, g_himg);
    cudaGetSymbolAddress((void**)&p_v3a, g_v3a);
    cudaGetSymbolAddress((void**)&p_v3b, g_v3b);
    cudaGetSymbolAddress((void**)&p_asrc, g_asrc);
    cudaGetSymbolAddress((void**)&p_adst, g_adst);
    cudaGetSymbolAddress((void**)&p_e, g_e);
    cudaGetSymbolAddress((void**)&p_al, g_al);
    cudaGetSymbolAddress((void**)&p_asrci, g_asrci);
    cudaGetSymbolAddress((void**)&p_adsti, g_adsti);
    cudaGetSymbolAddress((void**)&p_ei, g_ei_);
    cudaGetSymbolAddress((void**)&p_ali, g_ali);
    cudaGetSymbolAddress((void**)&p_patok, g_patok);
    cudaGetSymbolAddress((void**)&p_panp, g_panp);
    cudaGetSymbolAddress((void**)&p_tbar, g_tbar);
    cudaGetSymbolAddress((void**)&p_tbar2, g_tbar2);
    cudaGetSymbolAddress((void**)&p_offt, g_offt);
    cudaGetSymbolAddress((void**)&p_eidt, g_eidt);
    cudaGetSymbolAddress((void**)&p_offi, g_offi);
    cudaGetSymbolAddress((void**)&p_eidi, g_eidi);

    // CSR builds (edge sets are layer-invariant)
    k_csr<<<NB, 256>>>(ei_t, 2L*ET, LT, ET, p_offt, p_eidt, 1);
    k_csr<<<1,  256>>>(ei_i, 0L,    KK, EI, p_offi, p_eidi, 0);

    // a1 branch: pa_token softmax -> weighted t2 sum -> dot with v2
    k_pa    <<<NB, 1024>>>(t2, (long)LT*DD, LT, w1, b1, kpm, p_patok);
    k_wsum  <<<NB, 320 >>>(t2, (long)LT*DD, LT, p_patok, p_tbar);
    k_dotout<<<NB, 512 >>>(p_tbar, v2, out, 0);

    // c row (goes into g_x row LT)
    k_c<<<NB, 320>>>(score, t2, p_x);

    // txt GAT layers
    for (int i=0;i<NLAYERS;i++){
        const float* Ain = (i==0) ? t2 : p_y;
        k_gemm  <<<dim3(12,512), 256>>>(Ain, txtW + (size_t)i*DD*HD, p_h, NB*LT, HD, DD);
        k_scores<<<NB*LT, 160>>>(p_h, txtAS + i*HH*DD, txtAD + i*HH*DD, p_asrc, p_adst);
        k_edge  <<<(NB*ET*HH+255)/256, 256>>>(ei_t, 2L*ET, LT, ET, p_asrc, p_adst, p_e, NB*ET*HH);
        k_alpha <<<(NB*LT*HH+255)/256, 256>>>(p_offt, p_eidt, 1, p_e, p_al, LT, ET, NB*LT*HH);
        float* outp = (i==0) ? p_y : p_x;
        long ostride = (i==0) ? (long)LT*DD : (long)(LT+1)*DD;
        k_agg<<<dim3(LT,NB), 128>>>(p_h, p_al, p_offt, p_eidt, 1, ei_t, 2L*ET,
                                    txtB + i*DD, gnn, lng, lnb, outp, ostride, LT, ET);
    }

    // img GAT layers
    for (int i=0;i<NLAYERS;i++){
        const float* Ain = (i==0) ? v2 : p_v3a;
        k_gemm  <<<dim3(12,32), 256>>>(Ain, imgW + (size_t)i*DD*HD, p_himg, NB*KK, HD, DD);
        k_scores<<<NB*KK, 160>>>(p_himg, imgAS + i*HH*DD, imgAD + i*HH*DD, p_asrci, p_adsti);
        k_edge  <<<(NB*EI*HH+255)/256, 256>>>(ei_i, 0L, KK, EI, p_asrci, p_adsti, p_ei, NB*EI*HH);
        k_alpha <<<(NB*KK*HH+255)/256, 256>>>(p_offi, p_eidi, 0, p_ei, p_ali, KK, EI, NB*KK*HH);
        float* outp = (i==0) ? p_v3a : p_v3b;
        k_agg<<<dim3(KK,NB), 128>>>(p_himg, p_ali, p_offi, p_eidi, 0, ei_i, 0L,
                                    imgB + i*DD, nullptr, lng, lnb, outp, (long)KK*DD, KK, EI);
    }

    // a2 branch: pa_np softmax over (L+1) rows incl. c -> weighted sum -> dot with v3
    k_pa    <<<NB, 1024>>>(p_x, (long)(LT+1)*DD, LT+1, w2, b2, npm, p_panp);
    k_wsum  <<<NB, 320 >>>(p_x, (long)(LT+1)*DD, LT+1, p_panp, p_tbar2);
    k_dotout<<<NB, 512 >>>(p_tbar2, p_v3b, out, 64);
}